// round 17
// baseline (speedup 1.0000x reference)
#include <cuda_runtime.h>
#include <math.h>
#include <stdint.h>

typedef unsigned long long ull;

// Problem constants
#define B_DIM 64
#define S_DIM 4096
#define D_DIM 256
#define LN_EPS 1e-3f

// Pass1 tiling: 8 warps/CTA, 64 rows/warp -> 512 rows per CTA
#define WPB 8
#define RPW 64
#define ROWS_PER_CTA (WPB * RPW)           // 512
#define CTAS_PER_B (S_DIM / ROWS_PER_CTA)  // 8
#define PARTIALS_PER_B (CTAS_PER_B * WPB)  // 64
#define ITERS (RPW / 2)                    // 32
#define STAGES 3

// Pass2 split
#define SPLIT2 8
#define CHUNK2 (PARTIALS_PER_B / SPLIT2)   // 8

// Scratch. No max-tracking (LN-bounded scores; exp cannot overflow) ->
// partials combine linearly.
__device__ float g_acc[B_DIM * PARTIALS_PER_B * D_DIM];   // 4 MB
__device__ float g_l[B_DIM * PARTIALS_PER_B];
__device__ float g_part[SPLIT2 * B_DIM * D_DIM];          // 512 KB

// ---- packed f32x2 helpers (sm_100+/sm_103a FFMA2 path) ----
__device__ __forceinline__ ull pk2(float lo, float hi) {
    ull r;
    asm("mov.b64 %0, {%1, %2};" : "=l"(r) : "f"(lo), "f"(hi));
    return r;
}
__device__ __forceinline__ void upk2(float& lo, float& hi, ull v) {
    asm("mov.b64 {%0, %1}, %2;" : "=f"(lo), "=f"(hi) : "l"(v));
}
__device__ __forceinline__ ull add2(ull a, ull b) {
    ull r;
    asm("add.rn.f32x2 %0, %1, %2;" : "=l"(r) : "l"(a), "l"(b));
    return r;
}
__device__ __forceinline__ ull fma2(ull a, ull b, ull c) {
    ull r;
    asm("fma.rn.f32x2 %0, %1, %2, %3;" : "=l"(r) : "l"(a), "l"(b), "l"(c));
    return r;
}

__device__ __forceinline__ float warp_sum(float v) {
#pragma unroll
    for (int off = 16; off > 0; off >>= 1)
        v += __shfl_xor_sync(0xffffffffu, v, off);
    return v;
}

__device__ __forceinline__ void cp16(void* s, const void* g) {
    uint32_t sa = (uint32_t)__cvta_generic_to_shared(s);
    asm volatile("cp.async.cg.shared.global [%0], [%1], 16;\n" ::"r"(sa), "l"(g));
}

// ---------------------------------------------------------------------------
// Pass 1: single pass over x. Per-warp 3-stage cp.async smem pipeline (zero
// register cost, no block barrier: each lane consumes only its own swizzled
// 32 B). Arithmetic in packed f32x2 (FFMA2): per-lane sums 24 instead of 48,
// warp reduction 45 instead of 60, acc update 8 instead of 16.
// ---------------------------------------------------------------------------
__global__ __launch_bounds__(256, 4) void attn_pool_pass1(
    const float* __restrict__ x, const float* __restrict__ mask,
    const float* __restrict__ gamma, const float* __restrict__ beta,
    const float* __restrict__ w, const float* __restrict__ bias_p) {
    __shared__ __align__(1024) char sbuf[WPB][STAGES][2048];

    const int b = blockIdx.y;
    const int warp = threadIdx.x >> 5;
    const int lane = threadIdx.x & 31;
    const int d0 = lane * 8;

    // Per-lane gamma*w packed into 4 f32x2 pairs; warp-uniform GW, BW.
    ull gwp[4];
    float gwsum = 0.f, bwsum = 0.f;
#pragma unroll
    for (int i = 0; i < 4; i++) {
        float wlo = w[d0 + 2 * i], whi = w[d0 + 2 * i + 1];
        float glo = gamma[d0 + 2 * i] * wlo, ghi = gamma[d0 + 2 * i + 1] * whi;
        gwp[i] = pk2(glo, ghi);
        gwsum += glo + ghi;
        bwsum += beta[d0 + 2 * i] * wlo + beta[d0 + 2 * i + 1] * whi;
    }
    const float GW = warp_sum(gwsum);
    const float BW = warp_sum(bwsum) + bias_p[0];

    const int row0 = blockIdx.x * ROWS_PER_CTA + warp * RPW;
    const char* xb = (const char*)(x + ((size_t)b * S_DIM + row0) * D_DIM);
    const float* mb = mask + (size_t)b * S_DIM + row0;

    // Preload this warp's 64 mask addends (2 per lane), broadcast later.
    const float madd0 = (1.f - mb[lane]) * -1e9f;
    const float madd1 = (1.f - mb[lane + 32]) * -1e9f;

    // Swizzled intra-chunk byte offsets for this lane (conflict-free).
    const int o0 = lane * 32;
    const int sw0 = o0 ^ ((o0 >> 3) & 0x70);
    const int o1 = o0 + 16;
    const int sw1 = o1 ^ ((o1 >> 3) & 0x70);

    char* const wbuf = sbuf[warp][0];

    auto issue = [&](int it, int stage) {
        char* st = wbuf + stage * 2048;
        const char* g = xb + (size_t)it * 2048;
        cp16(st + sw0, g + o0);
        cp16(st + sw1, g + o1);
        cp16(st + 1024 + sw0, g + 1024 + o0);
        cp16(st + 1024 + sw1, g + 1024 + o1);
    };

    // Prologue: fill the pipeline.
    issue(0, 0); asm volatile("cp.async.commit_group;\n" ::: "memory");
    issue(1, 1); asm volatile("cp.async.commit_group;\n" ::: "memory");
    issue(2, 2); asm volatile("cp.async.commit_group;\n" ::: "memory");

    float l = 0.f;
    ull acc2[4];
#pragma unroll
    for (int i = 0; i < 4; i++) acc2[i] = pk2(0.f, 0.f);

    int stage = 0;
#pragma unroll 1
    for (int it = 0; it < ITERS; ++it) {
        asm volatile("cp.async.wait_group 2;\n" ::: "memory");

        // Row pair as packed f32x2 values (LDS.128 -> 2 ull regs each).
        const char* st = wbuf + stage * 2048;
        const ulonglong2 la0 = *reinterpret_cast<const ulonglong2*>(st + sw0);
        const ulonglong2 la1 = *reinterpret_cast<const ulonglong2*>(st + sw1);
        const ulonglong2 lc0 = *reinterpret_cast<const ulonglong2*>(st + 1024 + sw0);
        const ulonglong2 lc1 = *reinterpret_cast<const ulonglong2*>(st + 1024 + sw1);
        ull pa[4] = {la0.x, la0.y, la1.x, la1.y};
        ull pc[4] = {lc0.x, lc0.y, lc1.x, lc1.y};

        // Packed per-lane sums: 12 FFMA2-class ops per row.
        ull sxA2 = pk2(0.f, 0.f), sxxA2 = sxA2, sdA2 = sxA2;
        ull sxB2 = sxA2, sxxB2 = sxA2, sdB2 = sxA2;
#pragma unroll
        for (int i = 0; i < 4; i++) {
            sxA2 = add2(sxA2, pa[i]);
            sxxA2 = fma2(pa[i], pa[i], sxxA2);
            sdA2 = fma2(pa[i], gwp[i], sdA2);
            sxB2 = add2(sxB2, pc[i]);
            sxxB2 = fma2(pc[i], pc[i], sxxB2);
            sdB2 = fma2(pc[i], gwp[i], sdB2);
        }
        // Fold lo+hi, pack (rowA, rowB) pairs for the lane reduction.
        float lo, hi;
        upk2(lo, hi, sxA2);  const float sxA0 = lo + hi;
        upk2(lo, hi, sxB2);  ull sxP = pk2(sxA0, lo + hi);
        upk2(lo, hi, sxxA2); const float sxxA0 = lo + hi;
        upk2(lo, hi, sxxB2); ull sxxP = pk2(sxxA0, lo + hi);
        upk2(lo, hi, sdA2);  const float sdA0 = lo + hi;
        upk2(lo, hi, sdB2);  ull sdP = pk2(sdA0, lo + hi);

        // 5-round butterfly on 3 packed values: 2 SHFL + 1 packed add each.
#pragma unroll
        for (int off = 16; off > 0; off >>= 1) {
            sxP = add2(sxP, __shfl_xor_sync(0xffffffffu, sxP, off));
            sxxP = add2(sxxP, __shfl_xor_sync(0xffffffffu, sxxP, off));
            sdP = add2(sdP, __shfl_xor_sync(0xffffffffu, sdP, off));
        }
        float sxA, sxB, sxxA, sxxB, sdA, sdB;
        upk2(sxA, sxB, sxP);
        upk2(sxxA, sxxB, sxxP);
        upk2(sdA, sdB, sdP);

        // Mask addends for rows 2it, 2it+1 (warp-uniform select).
        const int r2 = 2 * it;
        const float msrc = (r2 < 32) ? madd0 : madd1;
        const float mA = __shfl_sync(0xffffffffu, msrc, r2 & 31);
        const float mB = __shfl_sync(0xffffffffu, msrc, (r2 + 1) & 31);

        const float muA = sxA * (1.f / D_DIM);
        const float muB = sxB * (1.f / D_DIM);
        const float varA = sxxA * (1.f / D_DIM) - muA * muA;
        const float varB = sxxB * (1.f / D_DIM) - muB * muB;
        const float rsA = rsqrtf(varA + LN_EPS);
        const float rsB = rsqrtf(varB + LN_EPS);
        const float sA = rsA * (sdA - muA * GW) + BW + mA;
        const float sB = rsB * (sdB - muB * GW) + BW + mB;

        const float pA = __expf(sA);
        const float pB = __expf(sB);
        l += pA + pB;

        // Packed accumulation: 8 FFMA2 instead of 16 FFMA.
        const ull pA2 = pk2(pA, pA);
        const ull pB2 = pk2(pB, pB);
#pragma unroll
        for (int i = 0; i < 4; i++)
            acc2[i] = fma2(pA2, pa[i], fma2(pB2, pc[i], acc2[i]));

        if (it + STAGES < ITERS) issue(it + STAGES, stage);
        asm volatile("cp.async.commit_group;\n" ::: "memory");

        stage = (stage == STAGES - 1) ? 0 : stage + 1;
    }
    asm volatile("cp.async.wait_all;\n" ::: "memory");

    // Write partial state.
    const int ip = blockIdx.x * WPB + warp;  // 0..63 within batch
    const size_t pbase = (size_t)b * PARTIALS_PER_B + ip;
    if (lane == 0) g_l[pbase] = l;
    ull* ab = reinterpret_cast<ull*>(g_acc + pbase * D_DIM + d0);
#pragma unroll
    for (int i = 0; i < 4; i++) ab[i] = acc2[i];
}

// ---------------------------------------------------------------------------
// Pass 2: grid (B, SPLIT2). Linear reduction of an 8-partial chunk over all
// 256 dims (coalesced across threads).
// ---------------------------------------------------------------------------
__global__ __launch_bounds__(256) void attn_pool_pass2() {
    const int b = blockIdx.x;
    const int split = blockIdx.y;
    const int t = threadIdx.x;

    const size_t pb = (size_t)b * PARTIALS_PER_B + (size_t)split * CHUNK2;
    const float* ab = g_acc + pb * D_DIM + t;
    float o = 0.f;
#pragma unroll
    for (int i = 0; i < CHUNK2; i++)
        o += ab[(size_t)i * D_DIM];
    g_part[((size_t)split * B_DIM + b) * D_DIM + t] = o;
}

// ---------------------------------------------------------------------------
// Pass 3: sum SPLIT2 split-partials + divide by total l. 64 CTAs.
// ---------------------------------------------------------------------------
__global__ __launch_bounds__(256) void attn_pool_pass3(float* __restrict__ out) {
    const int b = blockIdx.x;
    const int t = threadIdx.x;
    const int lane = t & 31;

    __shared__ float Lsh;
    if (t < 32) {
        const float* lp = g_l + (size_t)b * PARTIALS_PER_B;
        float s = lp[lane] + lp[lane + 32];
        s = warp_sum(s);
        if (lane == 0) Lsh = s;
    }
    __syncthreads();
    const float Linv = 1.f / Lsh;

    float o = 0.f;
#pragma unroll
    for (int s = 0; s < SPLIT2; s++)
        o += g_part[((size_t)s * B_DIM + b) * D_DIM + t];
    out[(size_t)b * D_DIM + t] = o * Linv;
}

extern "C" void kernel_launch(void* const* d_in, const int* in_sizes, int n_in,
                              void* d_out, int out_size) {
    const float* x = (const float*)d_in[0];      // [64,4096,256]
    const float* mask = (const float*)d_in[1];   // [64,4096]
    const float* gamma = (const float*)d_in[2];  // [256]
    const float* beta = (const float*)d_in[3];   // [256]
    const float* w = (const float*)d_in[4];      // [256]
    const float* bias = (const float*)d_in[5];   // scalar
    float* out = (float*)d_out;                  // [64,256]

    dim3 grid1(CTAS_PER_B, B_DIM);               // 8 x 64 = 512 CTAs -> 1 wave
    attn_pool_pass1<<<grid1, WPB * 32>>>(x, mask, gamma, beta, w, bias);
    dim3 grid2(B_DIM, SPLIT2);
    attn_pool_pass2<<<grid2, 256>>>();
    attn_pool_pass3<<<B_DIM, 256>>>(out);
}